// round 11
// baseline (speedup 1.0000x reference)
#include <cuda_runtime.h>
#include <cuda_fp16.h>
#include <math.h>
#include <stdint.h>

// N=50000, E=800000, C_IN=128, C_HID=128, C_OUT=64
#define CIN  128
#define CHID 128
#define COUT 64
#define MAXN 50048
#define MAXE 800000
#define NCHK 196
#define G1   148          // CSR-role blocks (sub-barrier group)
#define GALL 296          // total blocks (2 per SM)

// -------- scratch (device globals) --------
__device__ float g_deg[MAXN];
__device__ float g_dinv[MAXN];
__device__ int   g_cnt[MAXN];
__device__ int   g_off[MAXN + 1];
__device__ int   g_cur[MAXN];
__device__ int   g_part[NCHK + 4];
__device__ int   g_csr_src[MAXE];
__device__ float g_csr_norm[MAXE];
__device__ __half g_xw1h[(size_t)MAXN * CHID];
__device__ float  g_h  [(size_t)MAXN * CHID];
__device__ __half g_xw2h[(size_t)MAXN * COUT];
__device__ int   g_idx64;
__device__ unsigned long long g_bcnt;    // CSR-subset ticket counter (monotonic)
__device__ unsigned long long g_bbase;   // its base, handed off across replays
__device__ unsigned long long g_bcnt2;   // all-296 ticket counter
__device__ unsigned long long g_bbase2;  // its base

// -------- packed f32x2 helpers --------
#define FMA_F32X2(d, a, b, c) \
    asm("fma.rn.f32x2 %0, %1, %2, %3;" : "=l"(d) : "l"(a), "l"(b), "l"(c))
#define PACK_DUP_F32X2(out, f) \
    asm("mov.b64 %0, {%1, %1};" : "=l"(out) : "r"(__float_as_uint(f)))
#define UNPACK_F32X2(lo, hi, in) \
    asm("mov.b64 {%0, %1}, %2;" : "=r"(lo), "=r"(hi) : "l"(in))

__device__ __forceinline__ void edge_sd(const void* ei, int E, int e, int& s, int& d) {
    if (g_idx64) {
        const long long* p = (const long long*)ei;
        s = (int)p[e];
        d = (int)p[(size_t)E + e];
    } else {
        const int* p = (const int*)ei;
        s = p[e];
        d = p[E + e];
    }
}

// -------- ticket grid barriers --------
__device__ __forceinline__ void gbar148(unsigned long long bb, int idx) {
    __syncthreads();
    if (threadIdx.x == 0) {
        __threadfence();
        unsigned long long target = bb + (unsigned long long)idx * G1;
        unsigned long long t = atomicAdd(&g_bcnt, 1ULL);
        if (idx == 4 && t == target - 1)
            *(volatile unsigned long long*)&g_bbase = bb + 4ULL * G1;
        volatile unsigned long long* p = (volatile unsigned long long*)&g_bcnt;
        while (*p < target) __nanosleep(64);
        __threadfence();
    }
    __syncthreads();
}

__device__ __forceinline__ void gbar296(unsigned long long bb2, int idx) {
    __syncthreads();
    if (threadIdx.x == 0) {
        __threadfence();
        unsigned long long target = bb2 + (unsigned long long)idx * GALL;
        unsigned long long t = atomicAdd(&g_bcnt2, 1ULL);
        if (idx == 3 && t == target - 1)
            *(volatile unsigned long long*)&g_bbase2 = bb2 + 3ULL * GALL;
        volatile unsigned long long* p = (volatile unsigned long long*)&g_bcnt2;
        while (*p < target) __nanosleep(64);
        __threadfence();
    }
    __syncthreads();
}

// -------- GEMM tile body (f32x2 FMA), half output --------
template <int NC>
__device__ __forceinline__ void gemm_tile(const float* __restrict__ X,
                                          const float* __restrict__ W,
                                          __half* __restrict__ Y, int n, int row0,
                                          float (*Ws)[NC], float (*Xs)[132]) {
    const int K  = 128;
    const int KB = 32;
    const int NG = NC / 64;
    const int CT = NG * 4;

    int tid = threadIdx.x;
    int tx = tid & 15;
    int ty = tid >> 4;

    unsigned long long acc[4][CT];
#pragma unroll
    for (int i = 0; i < 4; i++)
#pragma unroll
        for (int j = 0; j < CT; j++) acc[i][j] = 0ull;

    for (int kt = 0; kt < K; kt += KB) {
        {
            const float4* W4 = (const float4*)(W + (size_t)kt * NC);
            float4* Ws4 = (float4*)&Ws[0][0];
#pragma unroll
            for (int i = tid; i < KB * NC / 4; i += 256) Ws4[i] = W4[i];
        }
#pragma unroll
        for (int i = 0; i < 4; i++) {
            int idx = tid + 256 * i;
            int r = idx >> 3, c = idx & 7;
            int row = row0 + r;
            float4 v = make_float4(0.f, 0.f, 0.f, 0.f);
            if (row < n) v = *(const float4*)&X[(size_t)row * K + kt + 4 * c];
            Xs[4 * c + 0][r] = v.x;
            Xs[4 * c + 1][r] = v.y;
            Xs[4 * c + 2][r] = v.z;
            Xs[4 * c + 3][r] = v.w;
        }
        __syncthreads();

#pragma unroll
        for (int k = 0; k < KB; k++) {
            const ulonglong2* xr2 = (const ulonglong2*)&Xs[k][ty * 8];
            ulonglong2 xa = xr2[0], xb = xr2[1];
            unsigned long long xp[4] = {xa.x, xa.y, xb.x, xb.y};
            unsigned long long wd[CT];
#pragma unroll
            for (int g = 0; g < NG; g++) {
                float4 w4 = *(const float4*)&Ws[k][g * 64 + tx * 4];
                PACK_DUP_F32X2(wd[g * 4 + 0], w4.x);
                PACK_DUP_F32X2(wd[g * 4 + 1], w4.y);
                PACK_DUP_F32X2(wd[g * 4 + 2], w4.z);
                PACK_DUP_F32X2(wd[g * 4 + 3], w4.w);
            }
#pragma unroll
            for (int i = 0; i < 4; i++)
#pragma unroll
                for (int j = 0; j < CT; j++)
                    FMA_F32X2(acc[i][j], xp[i], wd[j], acc[i][j]);
        }
        __syncthreads();
    }

#pragma unroll
    for (int i2 = 0; i2 < 4; i2++) {
        float lo[CT], hi[CT];
#pragma unroll
        for (int j = 0; j < CT; j++) {
            uint32_t l, h;
            UNPACK_F32X2(l, h, acc[i2][j]);
            lo[j] = __uint_as_float(l);
            hi[j] = __uint_as_float(h);
        }
        int rowa = row0 + ty * 8 + 2 * i2;
        int rowb = rowa + 1;
        if (rowa < n) {
#pragma unroll
            for (int g = 0; g < NG; g++) {
                __half2 p0 = __floats2half2_rn(lo[g * 4 + 0], lo[g * 4 + 1]);
                __half2 p1 = __floats2half2_rn(lo[g * 4 + 2], lo[g * 4 + 3]);
                uint2 o = {*(uint32_t*)&p0, *(uint32_t*)&p1};
                *(uint2*)&Y[(size_t)rowa * NC + g * 64 + tx * 4] = o;
            }
        }
        if (rowb < n) {
#pragma unroll
            for (int g = 0; g < NG; g++) {
                __half2 p0 = __floats2half2_rn(hi[g * 4 + 0], hi[g * 4 + 1]);
                __half2 p1 = __floats2half2_rn(hi[g * 4 + 2], hi[g * 4 + 3]);
                uint2 o = {*(uint32_t*)&p0, *(uint32_t*)&p1};
                *(uint2*)&Y[(size_t)rowb * NC + g * 64 + tx * 4] = o;
            }
        }
    }
}

__device__ __forceinline__ float softplus_f(float v) {
    return fmaxf(v, 0.0f) + log1pf(expf(-fabsf(v)));
}

// ==================== MEGA KERNEL ====================
__global__ void __launch_bounds__(256, 2)
k_mega(const float* __restrict__ x, const void* __restrict__ ei,
       const float* __restrict__ ew, const float* __restrict__ W1,
       const float* __restrict__ b1, const float* __restrict__ W2,
       const float* __restrict__ b2, float* __restrict__ out, int n, int E) {
    __shared__ float Ws[32][CHID];
    __shared__ float Xs[32][132];
    __shared__ int wsA[8], wsB[8], wbase[8];
    __shared__ int sh_cb;
    __shared__ unsigned long long sh_bb, sh_bb2;

    int tid = threadIdx.x;
    int lane = tid & 31, wid = tid >> 5;

    if (tid == 0) {
        sh_bb  = *(volatile unsigned long long*)&g_bbase;
        sh_bb2 = *(volatile unsigned long long*)&g_bbase2;
    }
    __syncthreads();
    unsigned long long bb = sh_bb, bb2 = sh_bb2;

    // ======= Phase 0: CSR build (blocks 0..147) || GEMM1 (blocks 148..295) =======
    if (blockIdx.x < G1) {
        int cid = blockIdx.x;
        const int NT = G1 * 256;

        // A: zero + idx64 detect
        for (int i = cid * 256 + tid; i < n; i += NT) { g_deg[i] = 0.0f; g_cnt[i] = 0; }
        if (cid == 0 && tid < 32) {
            const int* p = (const int*)ei;
            int words = 2 * E;
            int i1 = 1 + 2 * tid, i2 = 65 + 2 * tid;
            int nz = 0;
            if (i1 < words && p[i1] != 0) nz = 1;
            if (i2 < words && p[i2] != 0) nz = 1;
            unsigned b = __ballot_sync(0xFFFFFFFFu, nz);
            if (tid == 0) g_idx64 = (b == 0u) ? 1 : 0;
        }
        gbar148(bb, 1);

        // B: degree + count
        for (int e = cid * 256 + tid; e < E; e += NT) {
            int s, d;
            edge_sd(ei, E, e, s, d);
            atomicAdd(&g_deg[d], __ldg(&ew[e]));
            atomicAdd(&g_cnt[d], 1);
        }
        gbar148(bb, 2);

        // C: per-chunk partial sums
        int nch = (n + 255) >> 8;
        for (int chunk = cid; chunk < nch; chunk += G1) {
            int i = chunk * 256 + tid;
            int v = (i < n) ? __ldcg(&g_cnt[i]) : 0;
            int s = v;
#pragma unroll
            for (int o = 16; o > 0; o >>= 1) s += __shfl_down_sync(0xFFFFFFFFu, s, o);
            if (lane == 0) wsA[wid] = s;
            __syncthreads();
            if (tid == 0) {
                int tot = 0;
#pragma unroll
                for (int w = 0; w < 8; w++) tot += wsA[w];
                g_part[chunk] = tot;
            }
            __syncthreads();
        }
        gbar148(bb, 3);

        // D: downsweep + dinv
        for (int chunk = cid; chunk < nch; chunk += G1) {
            int acc = 0;
            for (int c = tid; c < chunk; c += 256) acc += __ldcg(&g_part[c]);
#pragma unroll
            for (int o = 16; o > 0; o >>= 1) acc += __shfl_down_sync(0xFFFFFFFFu, acc, o);
            if (lane == 0) wsA[wid] = acc;
            __syncthreads();
            if (tid == 0) {
                int b = 0;
#pragma unroll
                for (int w = 0; w < 8; w++) b += wsA[w];
                sh_cb = b;
            }
            __syncthreads();

            int i = chunk * 256 + tid;
            int v = (i < n) ? __ldcg(&g_cnt[i]) : 0;
            int s = v;
#pragma unroll
            for (int o = 1; o < 32; o <<= 1) {
                int t = __shfl_up_sync(0xFFFFFFFFu, s, o);
                if (lane >= o) s += t;
            }
            if (lane == 31) wsB[wid] = s;
            __syncthreads();
            if (tid == 0) {
                int a2 = 0;
#pragma unroll
                for (int w = 0; w < 8; w++) { wbase[w] = a2; a2 += wsB[w]; }
            }
            __syncthreads();
            if (i < n) {
                int ex = sh_cb + wbase[wid] + s - v;
                g_off[i] = ex;
                g_cur[i] = ex;
                g_dinv[i] = rsqrtf(__ldcg(&g_deg[i]) + 1.0f);
            }
            __syncthreads();
        }
        if (cid == 0 && tid == 0) g_off[n] = E;
        gbar148(bb, 4);

        // E: scatter
        for (int e = cid * 256 + tid; e < E; e += NT) {
            int s, d;
            edge_sd(ei, E, e, s, d);
            int pos = atomicAdd(&g_cur[d], 1);
            g_csr_src[pos]  = s;
            g_csr_norm[pos] = __ldcg(&g_dinv[s]) * __ldg(&ew[e]) * __ldcg(&g_dinv[d]);
        }
    } else {
        // GEMM1 role
        int ntiles = (n + 127) >> 7;
        for (int t = blockIdx.x - G1; t < ntiles; t += GALL - G1)
            gemm_tile<CHID>(x, W1, g_xw1h, n, t << 7, Ws, Xs);
    }
    gbar296(bb2, 1);

    // ======= Phase 1: agg1 (all blocks; half-warp per node, 8 ch/lane via uint4) =======
    {
        const uint4* __restrict__ xw = (const uint4*)g_xw1h;   // row = 16 uint4
        const int*   __restrict__ csr = g_csr_src;
        const float* __restrict__ nrm = g_csr_norm;
        int half = lane >> 4, sub = lane & 15;
        int gwarp = blockIdx.x * 8 + wid;
        int npairs = (n + 1) >> 1;
        for (int p = gwarp; p < npairs; p += GALL * 8) {
            int node = 2 * p + half;
            bool nv = node < n;
            int beg = nv ? g_off[node] : 0;
            int end = nv ? g_off[node + 1] : 0;
            float a0 = 0.f, a1 = 0.f, a2 = 0.f, a3 = 0.f;
            float a4 = 0.f, a5 = 0.f, a6 = 0.f, a7 = 0.f;
            int e = beg;
            for (; e + 2 <= end; e += 2) {
                int   s0 = __ldg(&csr[e]),  s1 = __ldg(&csr[e + 1]);
                float w0 = __ldg(&nrm[e]),  w1 = __ldg(&nrm[e + 1]);
                uint4 u0 = xw[(size_t)s0 * 16 + sub];
                uint4 u1 = xw[(size_t)s1 * 16 + sub];
                float2 f0 = __half22float2(*(__half2*)&u0.x);
                float2 f1 = __half22float2(*(__half2*)&u0.y);
                float2 f2 = __half22float2(*(__half2*)&u0.z);
                float2 f3 = __half22float2(*(__half2*)&u0.w);
                float2 g0 = __half22float2(*(__half2*)&u1.x);
                float2 g1 = __half22float2(*(__half2*)&u1.y);
                float2 g2 = __half22float2(*(__half2*)&u1.z);
                float2 g3 = __half22float2(*(__half2*)&u1.w);
                a0 += w0 * f0.x + w1 * g0.x;  a1 += w0 * f0.y + w1 * g0.y;
                a2 += w0 * f1.x + w1 * g1.x;  a3 += w0 * f1.y + w1 * g1.y;
                a4 += w0 * f2.x + w1 * g2.x;  a5 += w0 * f2.y + w1 * g2.y;
                a6 += w0 * f3.x + w1 * g3.x;  a7 += w0 * f3.y + w1 * g3.y;
            }
            if (e < end) {
                int   s = __ldg(&csr[e]);
                float w = __ldg(&nrm[e]);
                uint4 u = xw[(size_t)s * 16 + sub];
                float2 f0 = __half22float2(*(__half2*)&u.x);
                float2 f1 = __half22float2(*(__half2*)&u.y);
                float2 f2 = __half22float2(*(__half2*)&u.z);
                float2 f3 = __half22float2(*(__half2*)&u.w);
                a0 += w * f0.x; a1 += w * f0.y; a2 += w * f1.x; a3 += w * f1.y;
                a4 += w * f2.x; a5 += w * f2.y; a6 += w * f3.x; a7 += w * f3.y;
            }
            if (nv) {
                float di = g_dinv[node];
                float sn = di * di;
                uint4 u = xw[(size_t)node * 16 + sub];
                float2 f0 = __half22float2(*(__half2*)&u.x);
                float2 f1 = __half22float2(*(__half2*)&u.y);
                float2 f2 = __half22float2(*(__half2*)&u.z);
                float2 f3 = __half22float2(*(__half2*)&u.w);
                a0 += sn * f0.x; a1 += sn * f0.y; a2 += sn * f1.x; a3 += sn * f1.y;
                a4 += sn * f2.x; a5 += sn * f2.y; a6 += sn * f3.x; a7 += sn * f3.y;
                float4 bA = *(const float4*)&b1[sub * 8];
                float4 bB = *(const float4*)&b1[sub * 8 + 4];
                a0 += bA.x; a1 += bA.y; a2 += bA.z; a3 += bA.w;
                a4 += bB.x; a5 += bB.y; a6 += bB.z; a7 += bB.w;
                float4 oA, oB;
                oA.x = (a0 > 0.f) ? a0 : expm1f(a0);
                oA.y = (a1 > 0.f) ? a1 : expm1f(a1);
                oA.z = (a2 > 0.f) ? a2 : expm1f(a2);
                oA.w = (a3 > 0.f) ? a3 : expm1f(a3);
                oB.x = (a4 > 0.f) ? a4 : expm1f(a4);
                oB.y = (a5 > 0.f) ? a5 : expm1f(a5);
                oB.z = (a6 > 0.f) ? a6 : expm1f(a6);
                oB.w = (a7 > 0.f) ? a7 : expm1f(a7);
                *(float4*)&g_h[(size_t)node * CHID + sub * 8]     = oA;
                *(float4*)&g_h[(size_t)node * CHID + sub * 8 + 4] = oB;
            }
        }
    }
    gbar296(bb2, 2);

    // ======= Phase 2: GEMM2 (all blocks) =======
    {
        int ntiles = (n + 127) >> 7;
        float (*Ws64)[COUT] = (float (*)[COUT])&Ws[0][0];
        for (int t = blockIdx.x; t < ntiles; t += GALL)
            gemm_tile<COUT>(g_h, W2, g_xw2h, n, t << 7, Ws64, Xs);
    }
    gbar296(bb2, 3);

    // ======= Phase 3: agg2 (all blocks; half-warp per node, 4 ch/lane via uint2) =======
    {
        const uint2* __restrict__ xw = (const uint2*)g_xw2h;   // row = 16 uint2
        const int*   __restrict__ csr = g_csr_src;
        const float* __restrict__ nrm = g_csr_norm;
        int half = lane >> 4, sub = lane & 15;
        int gwarp = blockIdx.x * 8 + wid;
        int npairs = (n + 1) >> 1;
        for (int p = gwarp; p < npairs; p += GALL * 8) {
            int node = 2 * p + half;
            bool nv = node < n;
            int beg = nv ? g_off[node] : 0;
            int end = nv ? g_off[node + 1] : 0;
            float a0 = 0.f, a1 = 0.f, a2 = 0.f, a3 = 0.f;
            int e = beg;
            for (; e + 2 <= end; e += 2) {
                int   s0 = __ldg(&csr[e]),  s1 = __ldg(&csr[e + 1]);
                float w0 = __ldg(&nrm[e]),  w1 = __ldg(&nrm[e + 1]);
                uint2 u0 = xw[(size_t)s0 * 16 + sub];
                uint2 u1 = xw[(size_t)s1 * 16 + sub];
                float2 f0 = __half22float2(*(__half2*)&u0.x);
                float2 f1 = __half22float2(*(__half2*)&u0.y);
                float2 g0 = __half22float2(*(__half2*)&u1.x);
                float2 g1 = __half22float2(*(__half2*)&u1.y);
                a0 += w0 * f0.x + w1 * g0.x;  a1 += w0 * f0.y + w1 * g0.y;
                a2 += w0 * f1.x + w1 * g1.x;  a3 += w0 * f1.y + w1 * g1.y;
            }
            if (e < end) {
                int   s = __ldg(&csr[e]);
                float w = __ldg(&nrm[e]);
                uint2 u = xw[(size_t)s * 16 + sub];
                float2 f0 = __half22float2(*(__half2*)&u.x);
                float2 f1 = __half22float2(*(__half2*)&u.y);
                a0 += w * f0.x; a1 += w * f0.y; a2 += w * f1.x; a3 += w * f1.y;
            }
            if (nv) {
                float di = g_dinv[node];
                float sn = di * di;
                uint2 u = xw[(size_t)node * 16 + sub];
                float2 f0 = __half22float2(*(__half2*)&u.x);
                float2 f1 = __half22float2(*(__half2*)&u.y);
                a0 += sn * f0.x; a1 += sn * f0.y; a2 += sn * f1.x; a3 += sn * f1.y;
                float4 bv = *(const float4*)&b2[sub * 4];
                a0 += bv.x; a1 += bv.y; a2 += bv.z; a3 += bv.w;
                float4 o;
                o.x = softplus_f(a0) + 1e-4f;
                o.y = softplus_f(a1) + 1e-4f;
                o.z = softplus_f(a2) + 1e-4f;
                o.w = softplus_f(a3) + 1e-4f;
                *(float4*)&out[(size_t)node * COUT + sub * 4] = o;
            }
        }
    }
}

// -------- launcher --------
extern "C" void kernel_launch(void* const* d_in, const int* in_sizes, int n_in,
                              void* d_out, int out_size) {
    const float* x  = (const float*)d_in[0];
    const void*  ei = d_in[1];
    const float* ew = (const float*)d_in[2];
    const float* W1 = (const float*)d_in[3];
    const float* b1 = (const float*)d_in[4];
    const float* W2 = (const float*)d_in[5];
    const float* b2 = (const float*)d_in[6];
    float* out = (float*)d_out;

    int n = in_sizes[0] / CIN;   // 50000
    int E = in_sizes[2];         // 800000

    k_mega<<<GALL, 256>>>(x, ei, ew, W1, b1, W2, b2, out, n, E);
}

// round 12
// speedup vs baseline: 1.2556x; 1.2556x over previous
#include <cuda_runtime.h>
#include <cuda_fp16.h>
#include <math.h>
#include <stdint.h>

// N=50000, E=800000, C_IN=128, C_HID=128, C_OUT=64
#define CIN  128
#define CHID 128
#define COUT 64
#define MAXN 50048
#define MAXE 800000
#define NCHK 196
#define G1   148      // CSR blocks participating in grid barrier
#define GRID_FUSED 296

// -------- scratch (device globals) --------
__device__ float g_deg[MAXN];
__device__ float g_dinv[MAXN];
__device__ int   g_cnt[MAXN];
__device__ int   g_off[MAXN + 1];
__device__ int   g_cur[MAXN];
__device__ int   g_part[NCHK + 4];
__device__ int   g_csr_src[MAXE];
__device__ float g_csr_norm[MAXE];
__device__ __half g_xw1h[(size_t)MAXN * CHID];
__device__ float  g_h  [(size_t)MAXN * CHID];
__device__ __half g_xw2h[(size_t)MAXN * COUT];
__device__ int   g_idx64;
__device__ unsigned long long g_bcnt;   // monotonic barrier counter (never reset)
__device__ unsigned long long g_bbase;  // counter value at launch start (handed off)

// -------- packed f32x2 helpers --------
#define FMA_F32X2(d, a, b, c) \
    asm("fma.rn.f32x2 %0, %1, %2, %3;" : "=l"(d) : "l"(a), "l"(b), "l"(c))
#define PACK_DUP_F32X2(out, f) \
    asm("mov.b64 %0, {%1, %1};" : "=l"(out) : "r"(__float_as_uint(f)))
#define UNPACK_F32X2(lo, hi, in) \
    asm("mov.b64 {%0, %1}, %2;" : "=r"(lo), "=r"(hi) : "l"(in))

__device__ __forceinline__ void edge_sd(const void* ei, int E, int e, int& s, int& d) {
    if (g_idx64) {
        const long long* p = (const long long*)ei;
        s = (int)p[e];
        d = (int)p[(size_t)E + e];
    } else {
        const int* p = (const int*)ei;
        s = p[e];
        d = p[E + e];
    }
}

// -------- grid barrier over the G1 CSR blocks (monotonic ticket counter) --------
__device__ __forceinline__ void gbar(unsigned long long bb, int idx) {
    __syncthreads();
    if (threadIdx.x == 0) {
        __threadfence();
        unsigned long long target = bb + (unsigned long long)idx * G1;
        unsigned long long t = atomicAdd(&g_bcnt, 1ULL);
        if (idx == 4 && t == target - 1)
            *(volatile unsigned long long*)&g_bbase = bb + 4ULL * G1;
        volatile unsigned long long* p = (volatile unsigned long long*)&g_bcnt;
        while (*p < target) __nanosleep(64);
        __threadfence();
    }
    __syncthreads();
}

// -------- GEMM tile body: Y[row0..row0+127, :] = X @ W, f32x2 FMA, half out --------
template <int NC>
__device__ __forceinline__ void gemm_tile(const float* __restrict__ X,
                                          const float* __restrict__ W,
                                          __half* __restrict__ Y, int n, int row0,
                                          float (*Ws)[NC], float (*Xs)[132]) {
    const int K  = 128;
    const int KB = 32;
    const int NG = NC / 64;
    const int CT = NG * 4;

    int tid = threadIdx.x;
    int tx = tid & 15;
    int ty = tid >> 4;

    unsigned long long acc[4][CT];
#pragma unroll
    for (int i = 0; i < 4; i++)
#pragma unroll
        for (int j = 0; j < CT; j++) acc[i][j] = 0ull;

    for (int kt = 0; kt < K; kt += KB) {
        {
            const float4* W4 = (const float4*)(W + (size_t)kt * NC);
            float4* Ws4 = (float4*)&Ws[0][0];
#pragma unroll
            for (int i = tid; i < KB * NC / 4; i += 256) Ws4[i] = W4[i];
        }
#pragma unroll
        for (int i = 0; i < 4; i++) {
            int idx = tid + 256 * i;
            int r = idx >> 3, c = idx & 7;
            int row = row0 + r;
            float4 v = make_float4(0.f, 0.f, 0.f, 0.f);
            if (row < n) v = *(const float4*)&X[(size_t)row * K + kt + 4 * c];
            Xs[4 * c + 0][r] = v.x;
            Xs[4 * c + 1][r] = v.y;
            Xs[4 * c + 2][r] = v.z;
            Xs[4 * c + 3][r] = v.w;
        }
        __syncthreads();

#pragma unroll
        for (int k = 0; k < KB; k++) {
            const ulonglong2* xr2 = (const ulonglong2*)&Xs[k][ty * 8];
            ulonglong2 xa = xr2[0], xb = xr2[1];
            unsigned long long xp[4] = {xa.x, xa.y, xb.x, xb.y};
            unsigned long long wd[CT];
#pragma unroll
            for (int g = 0; g < NG; g++) {
                float4 w4 = *(const float4*)&Ws[k][g * 64 + tx * 4];
                PACK_DUP_F32X2(wd[g * 4 + 0], w4.x);
                PACK_DUP_F32X2(wd[g * 4 + 1], w4.y);
                PACK_DUP_F32X2(wd[g * 4 + 2], w4.z);
                PACK_DUP_F32X2(wd[g * 4 + 3], w4.w);
            }
#pragma unroll
            for (int i = 0; i < 4; i++)
#pragma unroll
                for (int j = 0; j < CT; j++)
                    FMA_F32X2(acc[i][j], xp[i], wd[j], acc[i][j]);
        }
        __syncthreads();
    }

#pragma unroll
    for (int i2 = 0; i2 < 4; i2++) {
        float lo[CT], hi[CT];
#pragma unroll
        for (int j = 0; j < CT; j++) {
            uint32_t l, h;
            UNPACK_F32X2(l, h, acc[i2][j]);
            lo[j] = __uint_as_float(l);
            hi[j] = __uint_as_float(h);
        }
        int rowa = row0 + ty * 8 + 2 * i2;
        int rowb = rowa + 1;
        if (rowa < n) {
#pragma unroll
            for (int g = 0; g < NG; g++) {
                __half2 p0 = __floats2half2_rn(lo[g * 4 + 0], lo[g * 4 + 1]);
                __half2 p1 = __floats2half2_rn(lo[g * 4 + 2], lo[g * 4 + 3]);
                uint2 o = {*(uint32_t*)&p0, *(uint32_t*)&p1};
                *(uint2*)&Y[(size_t)rowa * NC + g * 64 + tx * 4] = o;
            }
        }
        if (rowb < n) {
#pragma unroll
            for (int g = 0; g < NG; g++) {
                __half2 p0 = __floats2half2_rn(hi[g * 4 + 0], hi[g * 4 + 1]);
                __half2 p1 = __floats2half2_rn(hi[g * 4 + 2], hi[g * 4 + 3]);
                uint2 o = {*(uint32_t*)&p0, *(uint32_t*)&p1};
                *(uint2*)&Y[(size_t)rowb * NC + g * 64 + tx * 4] = o;
            }
        }
    }
}

// -------- FUSED: blocks 0..147 build CSR (5 phases); 148..295 run GEMM1 --------
__global__ void __launch_bounds__(256, 2)
k_fused(const float* __restrict__ x, const void* __restrict__ ei,
        const float* __restrict__ ew, const float* __restrict__ W1,
        __half* __restrict__ xw1, int n, int E) {
    __shared__ float Ws[32][CHID];
    __shared__ float Xs[32][132];
    __shared__ int wsA[8], wsB[8], wbase[8];
    __shared__ int sh_cb;
    __shared__ unsigned long long sh_bb;

    int tid = threadIdx.x;

    if (blockIdx.x >= G1) {
        int t = blockIdx.x - G1;
        int ntiles = (n + 127) >> 7;
        for (; t < ntiles; t += GRID_FUSED - G1)
            gemm_tile<CHID>(x, W1, xw1, n, t << 7, Ws, Xs);
        return;
    }

    int cid = blockIdx.x;
    int lane = tid & 31, wid = tid >> 5;
    const int NT = G1 * 256;

    if (tid == 0) sh_bb = *(volatile unsigned long long*)&g_bbase;
    __syncthreads();
    unsigned long long bb = sh_bb;

    // Phase A: zero + idx64 detect
    for (int i = cid * 256 + tid; i < n; i += NT) { g_deg[i] = 0.0f; g_cnt[i] = 0; }
    if (cid == 0 && tid < 32) {
        const int* p = (const int*)ei;
        int words = 2 * E;
        int i1 = 1 + 2 * tid, i2 = 65 + 2 * tid;
        int nz = 0;
        if (i1 < words && p[i1] != 0) nz = 1;
        if (i2 < words && p[i2] != 0) nz = 1;
        unsigned b = __ballot_sync(0xFFFFFFFFu, nz);
        if (tid == 0) g_idx64 = (b == 0u) ? 1 : 0;
    }
    gbar(bb, 1);

    // Phase B: degree + count
    for (int e = cid * 256 + tid; e < E; e += NT) {
        int s, d;
        edge_sd(ei, E, e, s, d);
        atomicAdd(&g_deg[d], __ldg(&ew[e]));
        atomicAdd(&g_cnt[d], 1);
    }
    gbar(bb, 2);

    // Phase C: per-chunk partial sums
    int nch = (n + 255) >> 8;
    for (int chunk = cid; chunk < nch; chunk += G1) {
        int i = chunk * 256 + tid;
        int v = (i < n) ? __ldcg(&g_cnt[i]) : 0;
        int s = v;
#pragma unroll
        for (int o = 16; o > 0; o >>= 1) s += __shfl_down_sync(0xFFFFFFFFu, s, o);
        if (lane == 0) wsA[wid] = s;
        __syncthreads();
        if (tid == 0) {
            int tot = 0;
#pragma unroll
            for (int w = 0; w < 8; w++) tot += wsA[w];
            g_part[chunk] = tot;
        }
        __syncthreads();
    }
    gbar(bb, 3);

    // Phase D: downsweep + dinv
    for (int chunk = cid; chunk < nch; chunk += G1) {
        int acc = 0;
        for (int c = tid; c < chunk; c += 256) acc += __ldcg(&g_part[c]);
#pragma unroll
        for (int o = 16; o > 0; o >>= 1) acc += __shfl_down_sync(0xFFFFFFFFu, acc, o);
        if (lane == 0) wsA[wid] = acc;
        __syncthreads();
        if (tid == 0) {
            int b = 0;
#pragma unroll
            for (int w = 0; w < 8; w++) b += wsA[w];
            sh_cb = b;
        }
        __syncthreads();

        int i = chunk * 256 + tid;
        int v = (i < n) ? __ldcg(&g_cnt[i]) : 0;
        int s = v;
#pragma unroll
        for (int o = 1; o < 32; o <<= 1) {
            int t = __shfl_up_sync(0xFFFFFFFFu, s, o);
            if (lane >= o) s += t;
        }
        if (lane == 31) wsB[wid] = s;
        __syncthreads();
        if (tid == 0) {
            int a2 = 0;
#pragma unroll
            for (int w = 0; w < 8; w++) { wbase[w] = a2; a2 += wsB[w]; }
        }
        __syncthreads();
        if (i < n) {
            int ex = sh_cb + wbase[wid] + s - v;
            g_off[i] = ex;
            g_cur[i] = ex;
            g_dinv[i] = rsqrtf(__ldcg(&g_deg[i]) + 1.0f);   // +1 self loop
        }
        __syncthreads();
    }
    if (cid == 0 && tid == 0) g_off[n] = E;
    gbar(bb, 4);

    // Phase E: scatter
    for (int e = cid * 256 + tid; e < E; e += NT) {
        int s, d;
        edge_sd(ei, E, e, s, d);
        int pos = atomicAdd(&g_cur[d], 1);
        g_csr_src[pos]  = s;
        g_csr_norm[pos] = __ldcg(&g_dinv[s]) * __ldg(&ew[e]) * __ldcg(&g_dinv[d]);
    }
}

// -------- standalone GEMM (layer 2) --------
__launch_bounds__(256, 2)
__global__ void k_gemm2(const float* __restrict__ X, const float* __restrict__ W,
                        __half* __restrict__ Y, int n) {
    __shared__ float Ws[32][COUT];
    __shared__ float Xs[32][132];
    gemm_tile<COUT>(X, W, Y, n, blockIdx.x * 128, Ws, Xs);
}

// -------- layer-1 aggregation: half-warp (16 lanes) per node, 8 ch/lane (uint4) --------
__launch_bounds__(256)
__global__ void k_agg1(const float* __restrict__ b1, int n) {
    int gh = (blockIdx.x * 256 + threadIdx.x) >> 4;   // global half-warp = node
    int sub = threadIdx.x & 15;
    if (gh >= n) return;
    int node = gh;

    const uint4* __restrict__ xw = (const uint4*)g_xw1h;   // row = 16 uint4
    const int*   __restrict__ csr = g_csr_src;
    const float* __restrict__ nrm = g_csr_norm;
    int beg = g_off[node], end = g_off[node + 1];

    float a0 = 0.f, a1 = 0.f, a2 = 0.f, a3 = 0.f;
    float a4 = 0.f, a5 = 0.f, a6 = 0.f, a7 = 0.f;
    int e = beg;
    for (; e + 2 <= end; e += 2) {
        int   s0 = __ldg(&csr[e]),  s1 = __ldg(&csr[e + 1]);
        float w0 = __ldg(&nrm[e]),  w1 = __ldg(&nrm[e + 1]);
        uint4 u0 = xw[(size_t)s0 * 16 + sub];
        uint4 u1 = xw[(size_t)s1 * 16 + sub];
        float2 f0 = __half22float2(*(__half2*)&u0.x);
        float2 f1 = __half22float2(*(__half2*)&u0.y);
        float2 f2 = __half22float2(*(__half2*)&u0.z);
        float2 f3 = __half22float2(*(__half2*)&u0.w);
        float2 g0 = __half22float2(*(__half2*)&u1.x);
        float2 g1 = __half22float2(*(__half2*)&u1.y);
        float2 g2 = __half22float2(*(__half2*)&u1.z);
        float2 g3 = __half22float2(*(__half2*)&u1.w);
        a0 += w0 * f0.x + w1 * g0.x;  a1 += w0 * f0.y + w1 * g0.y;
        a2 += w0 * f1.x + w1 * g1.x;  a3 += w0 * f1.y + w1 * g1.y;
        a4 += w0 * f2.x + w1 * g2.x;  a5 += w0 * f2.y + w1 * g2.y;
        a6 += w0 * f3.x + w1 * g3.x;  a7 += w0 * f3.y + w1 * g3.y;
    }
    if (e < end) {
        int   s = __ldg(&csr[e]);
        float w = __ldg(&nrm[e]);
        uint4 u = xw[(size_t)s * 16 + sub];
        float2 f0 = __half22float2(*(__half2*)&u.x);
        float2 f1 = __half22float2(*(__half2*)&u.y);
        float2 f2 = __half22float2(*(__half2*)&u.z);
        float2 f3 = __half22float2(*(__half2*)&u.w);
        a0 += w * f0.x; a1 += w * f0.y; a2 += w * f1.x; a3 += w * f1.y;
        a4 += w * f2.x; a5 += w * f2.y; a6 += w * f3.x; a7 += w * f3.y;
    }
    float di = g_dinv[node];
    float sn = di * di;
    {
        uint4 u = xw[(size_t)node * 16 + sub];
        float2 f0 = __half22float2(*(__half2*)&u.x);
        float2 f1 = __half22float2(*(__half2*)&u.y);
        float2 f2 = __half22float2(*(__half2*)&u.z);
        float2 f3 = __half22float2(*(__half2*)&u.w);
        a0 += sn * f0.x; a1 += sn * f0.y; a2 += sn * f1.x; a3 += sn * f1.y;
        a4 += sn * f2.x; a5 += sn * f2.y; a6 += sn * f3.x; a7 += sn * f3.y;
    }

    float4 bA = *(const float4*)&b1[sub * 8];
    float4 bB = *(const float4*)&b1[sub * 8 + 4];
    a0 += bA.x; a1 += bA.y; a2 += bA.z; a3 += bA.w;
    a4 += bB.x; a5 += bB.y; a6 += bB.z; a7 += bB.w;

    float4 oA, oB;
    oA.x = (a0 > 0.f) ? a0 : expm1f(a0);
    oA.y = (a1 > 0.f) ? a1 : expm1f(a1);
    oA.z = (a2 > 0.f) ? a2 : expm1f(a2);
    oA.w = (a3 > 0.f) ? a3 : expm1f(a3);
    oB.x = (a4 > 0.f) ? a4 : expm1f(a4);
    oB.y = (a5 > 0.f) ? a5 : expm1f(a5);
    oB.z = (a6 > 0.f) ? a6 : expm1f(a6);
    oB.w = (a7 > 0.f) ? a7 : expm1f(a7);
    *(float4*)&g_h[(size_t)node * CHID + sub * 8]     = oA;
    *(float4*)&g_h[(size_t)node * CHID + sub * 8 + 4] = oB;
}

// -------- layer-2 aggregation: half-warp per node, 4 ch/lane (uint2) --------
__device__ __forceinline__ float softplus_f(float v) {
    return fmaxf(v, 0.0f) + log1pf(expf(-fabsf(v)));
}

__launch_bounds__(256)
__global__ void k_agg2(const float* __restrict__ b2, float* __restrict__ out, int n) {
    int gh = (blockIdx.x * 256 + threadIdx.x) >> 4;
    int sub = threadIdx.x & 15;
    if (gh >= n) return;
    int node = gh;

    const uint2* __restrict__ xw = (const uint2*)g_xw2h;   // row = 16 uint2
    const int*   __restrict__ csr = g_csr_src;
    const float* __restrict__ nrm = g_csr_norm;
    int beg = g_off[node], end = g_off[node + 1];

    float a0 = 0.f, a1 = 0.f, a2 = 0.f, a3 = 0.f;
    int e = beg;
    for (; e + 2 <= end; e += 2) {
        int   s0 = __ldg(&csr[e]),  s1 = __ldg(&csr[e + 1]);
        float w0 = __ldg(&nrm[e]),  w1 = __ldg(&nrm[e + 1]);
        uint2 u0 = xw[(size_t)s0 * 16 + sub];
        uint2 u1 = xw[(size_t)s1 * 16 + sub];
        float2 f0 = __half22float2(*(__half2*)&u0.x);
        float2 f1 = __half22float2(*(__half2*)&u0.y);
        float2 g0 = __half22float2(*(__half2*)&u1.x);
        float2 g1 = __half22float2(*(__half2*)&u1.y);
        a0 += w0 * f0.x + w1 * g0.x;  a1 += w0 * f0.y + w1 * g0.y;
        a2 += w0 * f1.x + w1 * g1.x;  a3 += w0 * f1.y + w1 * g1.y;
    }
    if (e < end) {
        int   s = __ldg(&csr[e]);
        float w = __ldg(&nrm[e]);
        uint2 u = xw[(size_t)s * 16 + sub];
        float2 f0 = __half22float2(*(__half2*)&u.x);
        float2 f1 = __half22float2(*(__half2*)&u.y);
        a0 += w * f0.x; a1 += w * f0.y; a2 += w * f1.x; a3 += w * f1.y;
    }
    float di = g_dinv[node];
    float sn = di * di;
    {
        uint2 u = xw[(size_t)node * 16 + sub];
        float2 f0 = __half22float2(*(__half2*)&u.x);
        float2 f1 = __half22float2(*(__half2*)&u.y);
        a0 += sn * f0.x; a1 += sn * f0.y; a2 += sn * f1.x; a3 += sn * f1.y;
    }

    float4 bv = *(const float4*)&b2[sub * 4];
    a0 += bv.x; a1 += bv.y; a2 += bv.z; a3 += bv.w;

    float4 o;
    o.x = softplus_f(a0) + 1e-4f;
    o.y = softplus_f(a1) + 1e-4f;
    o.z = softplus_f(a2) + 1e-4f;
    o.w = softplus_f(a3) + 1e-4f;
    *(float4*)&out[(size_t)node * COUT + sub * 4] = o;
}

// -------- launcher --------
extern "C" void kernel_launch(void* const* d_in, const int* in_sizes, int n_in,
                              void* d_out, int out_size) {
    const float* x  = (const float*)d_in[0];
    const void*  ei = d_in[1];
    const float* ew = (const float*)d_in[2];
    const float* W1 = (const float*)d_in[3];
    const float* b1 = (const float*)d_in[4];
    const float* W2 = (const float*)d_in[5];
    const float* b2 = (const float*)d_in[6];
    float* out = (float*)d_out;

    int n = in_sizes[0] / CIN;   // 50000
    int E = in_sizes[2];         // 800000

    void *xw1p, *hp, *xw2p;
    cudaGetSymbolAddress(&xw1p, g_xw1h);
    cudaGetSymbolAddress(&hp,   g_h);
    cudaGetSymbolAddress(&xw2p, g_xw2h);

    int ab = (n * 16 + 255) / 256;   // half-warp per node: 3125 blocks
    int gb = (n + 127) / 128;

    k_fused<<<GRID_FUSED, 256>>>(x, ei, ew, W1, (__half*)xw1p, n, E);
    k_agg1<<<ab, 256>>>(b1, n);
    k_gemm2<<<gb, 256>>>((const float*)hp, W2, (__half*)xw2p, n);
    k_agg2<<<ab, 256>>>(b2, out, n);
}